// round 5
// baseline (speedup 1.0000x reference)
#include <cuda_runtime.h>
#include <math.h>
#include <float.h>

#define NODES 10242
#define NG    16380
#define LATN  91
#define LONN  180
#define CH    64
#define BATCH 4

#define NBINS 128
#define BINW  (2.0f / NBINS)

// Scratch (no cudaMalloc allowed)
__device__ int    g_binStart[NBINS + 1];
__device__ int    g_binCur[NBINS];
__device__ float4 g_sorted[NODES];      // {x,y,z,m2} z-binned
__device__ int    g_sidx[NODES];        // original index of sorted node
__device__ float  g_knw[NG * 8];
__device__ int    g_kni[NG * 8];

__device__ __forceinline__ int zbin(float z) {
    int b = (int)((z + 1.0f) * (NBINS * 0.5f));
    return min(max(b, 0), NBINS - 1);
}

// ---------------------------------------------------------------------------
// Kernel 1: histogram z-bins (smem atomics) + exclusive scan. One block.
// ---------------------------------------------------------------------------
__global__ __launch_bounds__(256) void hist_scan_kernel(const float* __restrict__ mv) {
    __shared__ int h[NBINS];
    const int tid = threadIdx.x;
    if (tid < NBINS) h[tid] = 0;
    __syncthreads();
    for (int i = tid; i < NODES; i += 256)
        atomicAdd(&h[zbin(mv[3 * i + 2])], 1);
    __syncthreads();
    if (tid == 0) {
        int acc = 0;
        for (int k = 0; k < NBINS; ++k) {
            g_binStart[k] = acc;
            g_binCur[k]   = acc;
            acc += h[k];
        }
        g_binStart[NBINS] = acc;
    }
}

// ---------------------------------------------------------------------------
// Kernel 2: scatter nodes into z-bin order; pack {x,y,z,m2} with the
// reference's exact rounding (square + sequential add).
// ---------------------------------------------------------------------------
__global__ __launch_bounds__(256) void scatter_kernel(const float* __restrict__ mv) {
    int i = blockIdx.x * 256 + threadIdx.x;
    if (i < NODES) {
        float x = mv[3*i], y = mv[3*i+1], z = mv[3*i+2];
        float m2 = __fadd_rn(__fadd_rn(__fmul_rn(x,x), __fmul_rn(y,y)), __fmul_rn(z,z));
        int pos = atomicAdd(&g_binCur[zbin(z)], 1);
        g_sorted[pos] = make_float4(x, y, z, m2);
        g_sidx[pos]   = i;
    }
}

// ---------------------------------------------------------------------------
// KNN: one WARP per grid point; block = 4 warps = 4 adjacent lons of one lat
// row (z-window block-uniform). Candidate chunks staged in smem; lanes split
// each chunk 32-ways. Per-lane top-8 via an unconditional predicated
// compare-exchange cascade, lex-ordered on (d2, original_index) == the stable
// tie-break of jax.lax.top_k. d2 uses the reference's exact rounding:
//   d2 = fsub(fadd(g2, m2), fmul(2, fmaf(gz,mz, fmaf(gy,my, fmul(gx,mx)))))
// Ring termination: dmin^2 > max_warps(min_lanes(dd[7])) + 1e-5 is safe
// because min over lanes of a lane's 8th-best >= the warp's true 8th-best.
// ---------------------------------------------------------------------------
#define KWARPS 4
#define KT     (KWARPS * 32)

__device__ __forceinline__ bool lex_less(float a, int ai, float b, int bi) {
    return (a < b) || (a == b && ai < bi);
}

__global__ __launch_bounds__(KT) void knn_kernel(const float* __restrict__ lat,
                                                 const float* __restrict__ lon) {
    __shared__ float4 s_nd[KT];
    __shared__ int    s_id[KT];
    __shared__ float  s_red[KWARPS];

    const int tid   = threadIdx.x;
    const int lane  = tid & 31;
    const int wid   = tid >> 5;
    const int row   = blockIdx.x / (LONN / KWARPS);
    const int li    = (blockIdx.x % (LONN / KWARPS)) * KWARPS + wid;

    const float la = lat[row];
    const float lo = lon[li];
    const float cl = cosf(la);
    const float x  = __fmul_rn(cl, cosf(lo));
    const float y  = __fmul_rn(cl, sinf(lo));
    const float z  = sinf(la);
    const float g2 = __fadd_rn(__fadd_rn(__fmul_rn(x,x), __fmul_rn(y,y)), __fmul_rn(z,z));

    float dd[8];  // ascending by (d2, idx)
    int   xi[8];
#pragma unroll
    for (int j = 0; j < 8; ++j) { dd[j] = FLT_MAX; xi[j] = 0x7fffffff; }

    const float z0 = z;                  // block-uniform (same lat row)
    const int   b0 = zbin(z0);

    auto process_bin = [&](int bin) {
        const int s = g_binStart[bin];
        const int e = g_binStart[bin + 1];
        for (int base = s; base < e; base += KT) {     // block-uniform bounds
            const int n = min(KT, e - base);
            __syncthreads();
            if (tid < n) { s_nd[tid] = g_sorted[base + tid]; s_id[tid] = g_sidx[base + tid]; }
            __syncthreads();
            for (int j = lane; j < n; j += 32) {       // lanes split the chunk
                float4 p = s_nd[j];
                float v  = __fsub_rn(__fadd_rn(g2, p.w),
                           __fmul_rn(2.0f, __fmaf_rn(z, p.z,
                                           __fmaf_rn(y, p.y,
                                           __fmul_rn(x, p.x)))));
                int vi = s_id[j];
                // branch-free stable insert (compare-exchange cascade)
#pragma unroll
                for (int t = 0; t < 8; ++t) {
                    bool sw = lex_less(v, vi, dd[t], xi[t]);
                    float nv = sw ? dd[t] : v;
                    int   ni = sw ? xi[t] : vi;
                    dd[t] = sw ? v  : dd[t];
                    xi[t] = sw ? vi : xi[t];
                    v = nv; vi = ni;
                }
            }
        }
    };

    for (int r = 0; r < NBINS; ++r) {
        const int bl = b0 - r, br = b0 + r;
        if (bl < 0 && br >= NBINS) break;              // everything scanned
        if (bl >= 0) process_bin(bl);
        if (r > 0 && br < NBINS) process_bin(br);

        // distance from z0 to nearest UNSCANNED bin edge
        float dL = (bl > 0)         ? (z0 - (-1.0f + bl * BINW))       : FLT_MAX;
        float dR = (br < NBINS - 1) ? ((-1.0f + (br + 1) * BINW) - z0) : FLT_MAX;
        float dmin = fminf(dL, dR);
        if (dmin == FLT_MAX) break;                    // no unscanned bins remain

        // per-warp upper bound on true 8th-best: min over lanes of dd[7]
        float bw = dd[7];
#pragma unroll
        for (int off = 16; off > 0; off >>= 1)
            bw = fminf(bw, __shfl_xor_sync(0xffffffffu, bw, off));
        __syncthreads();
        if (lane == 0) s_red[wid] = bw;
        __syncthreads();
        float wm = s_red[0];
#pragma unroll
        for (int k = 1; k < KWARPS; ++k) wm = fmaxf(wm, s_red[k]);

        if (dmin * dmin > wm + 1e-5f) break;           // uniform decision
    }

    // warp-merge: 8 rounds of lex argmin over lane heads (stable top-8)
    float myd = 0.f; int myi = 0;
#pragma unroll
    for (int r = 0; r < 8; ++r) {
        float bv = dd[0]; int bi = xi[0]; int bl = lane;
#pragma unroll
        for (int off = 16; off > 0; off >>= 1) {
            float ov = __shfl_down_sync(0xffffffffu, bv, off);
            int   oi = __shfl_down_sync(0xffffffffu, bi, off);
            int   ol = __shfl_down_sync(0xffffffffu, bl, off);
            if (lex_less(ov, oi, bv, bi)) { bv = ov; bi = oi; bl = ol; }
        }
        bv = __shfl_sync(0xffffffffu, bv, 0);
        bi = __shfl_sync(0xffffffffu, bi, 0);
        bl = __shfl_sync(0xffffffffu, bl, 0);
        if (lane == bl) {  // winner pops its head
#pragma unroll
            for (int j = 0; j < 7; ++j) { dd[j] = dd[j+1]; xi[j] = xi[j+1]; }
            dd[7] = FLT_MAX; xi[7] = 0x7fffffff;
        }
        if (lane == r) { myd = bv; myi = bi; }
    }

    // softmax over -dist among the 8 (lanes 0..7); rank0 = nearest
    float dist = sqrtf(fmaxf(myd, 1e-12f));
    float dmn  = __shfl_sync(0xffffffffu, dist, 0);
    float w = 0.f;
    if (lane < 8) w = expf(__fsub_rn(dmn, dist));
    float s = w;
#pragma unroll
    for (int off = 16; off > 0; off >>= 1) s += __shfl_xor_sync(0xffffffffu, s, off);
    const int g = row * LONN + li;
    if (lane < 8) {
        g_knw[g * 8 + lane] = __fdiv_rn(w, s);
        g_kni[g * 8 + lane] = myi;
    }
}

// ---------------------------------------------------------------------------
// Gather + weighted combine + 64x64 linear + NCHW store (unchanged — passed).
// ---------------------------------------------------------------------------
__global__ __launch_bounds__(256) void gather_kernel(const float* __restrict__ M,
                                                     const float* __restrict__ W,
                                                     const float* __restrict__ bias,
                                                     float* __restrict__ out) {
    __shared__ float s_w[8][8];
    __shared__ int   s_i[8][8];
    __shared__ float s_W[64 * 65];                       // s_W[c*65+c'] = W[c'][c]
    __shared__ __align__(16) float s_it[BATCH * CH * 8]; // [b][c][g], pitch 8

    const int tid = threadIdx.x;
    const int g0  = blockIdx.x * 8;

    for (int i = tid; i < CH * CH; i += 256) {
        int cp = i >> 6;
        int c  = i & 63;
        s_W[c * 65 + cp] = W[i];
    }
    if (tid < 64) {
        int gg = tid >> 3, k = tid & 7;
        int g = g0 + gg;
        if (g < NG) { s_w[gg][k] = g_knw[g * 8 + k]; s_i[gg][k] = g_kni[g * 8 + k]; }
        else        { s_w[gg][k] = 0.f;              s_i[gg][k] = 0; }
    }
    __syncthreads();

    const int b = tid >> 6;
    const int c = tid & 63;

    const float* Mb = M + (size_t)b * NODES * CH + c;
    float r[8];
#pragma unroll
    for (int gg = 0; gg < 8; ++gg) {
        float a = 0.f;
#pragma unroll
        for (int k = 0; k < 8; ++k)
            a = __fmaf_rn(s_w[gg][k], Mb[(size_t)s_i[gg][k] * CH], a);
        r[gg] = a;
    }
    float* ip = &s_it[(b * CH + c) * 8];
    ((float4*)ip)[0] = make_float4(r[0], r[1], r[2], r[3]);
    ((float4*)ip)[1] = make_float4(r[4], r[5], r[6], r[7]);
    __syncthreads();

    float a[8];
    const float bv = bias[c];
#pragma unroll
    for (int gg = 0; gg < 8; ++gg) a[gg] = bv;
    const float* ib = &s_it[b * CH * 8];
#pragma unroll 8
    for (int cc = 0; cc < CH; ++cc) {
        float4 v0 = ((const float4*)(ib + cc * 8))[0];
        float4 v1 = ((const float4*)(ib + cc * 8))[1];
        float w = s_W[cc * 65 + c];
        a[0] = __fmaf_rn(w, v0.x, a[0]); a[1] = __fmaf_rn(w, v0.y, a[1]);
        a[2] = __fmaf_rn(w, v0.z, a[2]); a[3] = __fmaf_rn(w, v0.w, a[3]);
        a[4] = __fmaf_rn(w, v1.x, a[4]); a[5] = __fmaf_rn(w, v1.y, a[5]);
        a[6] = __fmaf_rn(w, v1.z, a[6]); a[7] = __fmaf_rn(w, v1.w, a[7]);
    }

    float* op = out + (size_t)(b * CH + c) * NG + g0;
    if (g0 + 8 <= NG) {
        ((float4*)op)[0] = make_float4(a[0], a[1], a[2], a[3]);
        ((float4*)op)[1] = make_float4(a[4], a[5], a[6], a[7]);
    } else {
#pragma unroll
        for (int gg = 0; gg < 8; ++gg)
            if (g0 + gg < NG) op[gg] = a[gg];
    }
}

// ---------------------------------------------------------------------------
extern "C" void kernel_launch(void* const* d_in, const int* in_sizes, int n_in,
                              void* d_out, int out_size) {
    const float* mesh_output   = (const float*)d_in[0];  // (4,10242,64)
    const float* mesh_vertices = (const float*)d_in[1];  // (10242,3)
    const float* lat           = (const float*)d_in[2];  // (91,)
    const float* lon           = (const float*)d_in[3];  // (180,)
    const float* W             = (const float*)d_in[4];  // (64,64)
    const float* bvec          = (const float*)d_in[5];  // (64,)
    float* out = (float*)d_out;                          // (4,64,91,180)

    hist_scan_kernel<<<1, 256>>>(mesh_vertices);
    scatter_kernel<<<(NODES + 255) / 256, 256>>>(mesh_vertices);
    knn_kernel<<<LATN * (LONN / KWARPS), KT>>>(lat, lon);
    gather_kernel<<<(NG + 7) / 8, 256>>>(mesh_output, W, bvec, out);
}

// round 6
// speedup vs baseline: 1.9013x; 1.9013x over previous
#include <cuda_runtime.h>
#include <math.h>
#include <float.h>

#define NODES 10242
#define NROWS 40968          // BATCH*NODES
#define NG    16380
#define LATN  91
#define LONN  180
#define CH    64
#define BATCH 4

// 2D bins: lon-major so each (lonbin, z-range) scan is ONE contiguous run
#define ZB    64
#define LB    32
#define NBIN2 (ZB*LB)
#define ZW    (2.0f/ZB)
#define LONW  (6.28318530717958647f/LB)
#define TCUT  0.02f          // prune bar on chord^2 (8-NN radius^2 with huge margin)
#define DZW   0.14142136f    // sqrt(TCUT)
#define PIF   3.14159274f

// Scratch (no cudaMalloc allowed)
__device__ int    g_binCnt[NBIN2];
__device__ int    g_binStart[NBIN2 + 1];
__device__ int    g_binCur[NBIN2];
__device__ float4 g_sorted[NODES];      // {x,y,z,m2} bin-sorted
__device__ int    g_sidx[NODES];        // original index
__device__ float  g_knw[NG * 8];
__device__ int    g_kni[NG * 8];
__device__ float  g_WT[CH * CH];        // g_WT[c*64+c'] = W[c'][c]
__device__ float  g_MW[NROWS * CH];     // M @ W^T  (10.5 MB, L2-resident)

__device__ __forceinline__ int zbin(float z) {
    int b = (int)((z + 1.0f) * (ZB * 0.5f));
    return min(max(b, 0), ZB - 1);
}
__device__ __forceinline__ int lonbin(float phi) {
    int b = (int)(phi * (1.0f / LONW));
    return min(max(b, 0), LB - 1);
}
__device__ __forceinline__ bool lex_less(float a, int ai, float b, int bi) {
    return (a < b) || (a == b && ai < bi);
}

// ---------------------------------------------------------------------------
// Zero bins + transpose W (folded). grid 8 x 256.
// ---------------------------------------------------------------------------
__global__ void zero_tw_kernel(const float* __restrict__ W) {
    int i = blockIdx.x * 256 + threadIdx.x;          // 0..2047
    g_binCnt[i] = 0;
#pragma unroll
    for (int k = 0; k < 2; ++k) {
        int e = i * 2 + k;                           // 0..4095
        int cp = e >> 6, c = e & 63;
        g_WT[c * 64 + cp] = W[e];
    }
}

// ---------------------------------------------------------------------------
__global__ void hist_kernel(const float* __restrict__ mv) {
    int i = blockIdx.x * 256 + threadIdx.x;
    if (i < NODES) {
        float x = mv[3*i], y = mv[3*i+1], z = mv[3*i+2];
        float phi = atan2f(y, x);
        if (phi < 0.f) phi += 6.28318530717958647f;
        atomicAdd(&g_binCnt[lonbin(phi) * ZB + zbin(z)], 1);
    }
}

// Parallel exclusive scan of 2048 bin counts. One block of 256.
__global__ __launch_bounds__(256) void scan_kernel() {
    __shared__ int ps[256];
    const int t = threadIdx.x;
    int loc[8]; int s = 0;
#pragma unroll
    for (int k = 0; k < 8; ++k) { loc[k] = g_binCnt[t * 8 + k]; s += loc[k]; }
    ps[t] = s;
    __syncthreads();
    for (int off = 1; off < 256; off <<= 1) {
        int v = (t >= off) ? ps[t - off] : 0;
        __syncthreads();
        ps[t] += v;
        __syncthreads();
    }
    int run = ps[t] - s;                             // exclusive prefix
#pragma unroll
    for (int k = 0; k < 8; ++k) {
        g_binStart[t * 8 + k] = run;
        g_binCur[t * 8 + k]   = run;
        run += loc[k];
    }
    if (t == 255) g_binStart[NBIN2] = run;
}

// Scatter into bin order; pack {x,y,z,m2} with the reference's exact rounding.
__global__ void scatter_kernel(const float* __restrict__ mv) {
    int i = blockIdx.x * 256 + threadIdx.x;
    if (i < NODES) {
        float x = mv[3*i], y = mv[3*i+1], z = mv[3*i+2];
        float phi = atan2f(y, x);
        if (phi < 0.f) phi += 6.28318530717958647f;
        float m2 = __fadd_rn(__fadd_rn(__fmul_rn(x,x), __fmul_rn(y,y)), __fmul_rn(z,z));
        int pos = atomicAdd(&g_binCur[lonbin(phi) * ZB + zbin(z)], 1);
        g_sorted[pos] = make_float4(x, y, z, m2);
        g_sidx[pos]   = i;
    }
}

// ---------------------------------------------------------------------------
// GEMM: g_MW[r][c'] = sum_c M[r][c] * W[c'][c], r over 40968 fused (b,node)
// rows. Block = 32 rows, 256 threads = (row, c'-group-of-8). A tile in smem
// (pitch 65, conflict-free); W^T rows read via LDG float4 (L1-hot 16KB).
// ---------------------------------------------------------------------------
__global__ __launch_bounds__(256) void gemm_kernel(const float* __restrict__ M) {
    __shared__ float s_A[32 * 65];
    const int tid = threadIdx.x;
    const int r0  = blockIdx.x * 32;

    for (int i = tid; i < 32 * 64; i += 256) {
        int r = i >> 6, c = i & 63;
        int row = min(r0 + r, NROWS - 1);
        s_A[r * 65 + c] = M[(size_t)row * 64 + c];
    }
    __syncthreads();

    const int r  = tid >> 3;        // 0..31
    const int cg = tid & 7;         // 0..7 -> c' = cg*8 .. cg*8+7
    float acc[8];
#pragma unroll
    for (int j = 0; j < 8; ++j) acc[j] = 0.f;

    const float* ar = &s_A[r * 65];
#pragma unroll 8
    for (int cc = 0; cc < 64; ++cc) {
        float a = ar[cc];                                   // broadcast x4
        float4 w0 = *(const float4*)&g_WT[cc * 64 + cg * 8];
        float4 w1 = *(const float4*)&g_WT[cc * 64 + cg * 8 + 4];
        acc[0] = __fmaf_rn(a, w0.x, acc[0]); acc[1] = __fmaf_rn(a, w0.y, acc[1]);
        acc[2] = __fmaf_rn(a, w0.z, acc[2]); acc[3] = __fmaf_rn(a, w0.w, acc[3]);
        acc[4] = __fmaf_rn(a, w1.x, acc[4]); acc[5] = __fmaf_rn(a, w1.y, acc[5]);
        acc[6] = __fmaf_rn(a, w1.z, acc[6]); acc[7] = __fmaf_rn(a, w1.w, acc[7]);
    }
    int row = r0 + r;
    if (row < NROWS) {
        float* op = &g_MW[(size_t)row * 64 + cg * 8];
        ((float4*)op)[0] = make_float4(acc[0], acc[1], acc[2], acc[3]);
        ((float4*)op)[1] = make_float4(acc[4], acc[5], acc[6], acc[7]);
    }
}

// ---------------------------------------------------------------------------
// KNN: one warp per grid point, no smem, no barriers. Scan the 2D bin box
// {|dz| <= DZW} x {|dphi| <= dphi_max}, where the lon window is derived from
// d^2 >= 2*rq*rn*(1-cos dphi) > TCUT with rn = min radius over the z-band
// (pole-safe: window -> full circle as rq*rn -> 0). Lists prefilled with
// TCUT so only true-near candidates (~51) ever insert; insert is a rare
// branchy 8-stage lex cascade. d2 uses the reference's exact rounding and
// lex (d2, idx) stable compare -> selected set == jax.lax.top_k's.
// ---------------------------------------------------------------------------
__global__ __launch_bounds__(256) void knn_kernel(const float* __restrict__ lat,
                                                  const float* __restrict__ lon) {
    const int w = blockIdx.x * 8 + (threadIdx.x >> 5);
    if (w >= NG) return;
    const int lane = threadIdx.x & 31;
    const int row  = w / LONN;
    const int li   = w - row * LONN;

    const float la = lat[row];
    const float lo = lon[li];
    const float cl = cosf(la);
    const float x  = __fmul_rn(cl, cosf(lo));
    const float y  = __fmul_rn(cl, sinf(lo));
    const float z  = sinf(la);
    const float g2 = __fadd_rn(__fadd_rn(__fmul_rn(x,x), __fmul_rn(y,y)), __fmul_rn(z,z));

    float dd[8]; int xi[8];
#pragma unroll
    for (int j = 0; j < 8; ++j) { dd[j] = TCUT; xi[j] = 0x7fffffff; }

    // z band
    const int zlo = zbin(z - DZW);
    const int zhi = zbin(z + DZW);

    // lon window (block of bins intersecting [lo-dphi, lo+dphi])
    const float rq   = fabsf(cl);
    const float zext = fminf(1.0f, fabsf(z) + DZW + ZW);
    const float rn2  = 1.0f - zext * zext;
    const float rnm  = rn2 > 0.f ? sqrtf(rn2) : 0.f;
    const float den  = 2.0f * rq * rnm;
    float dphi;
    if (den < 1e-6f) dphi = PIF;
    else {
        float ca = 1.0f - TCUT / den;
        dphi = (ca <= -1.0f) ? PIF : acosf(fminf(ca, 1.0f));
    }
    dphi += 1e-3f;                                   // binning-jitter margin
    int lb_lo = (int)floorf((lo - dphi) * (1.0f / LONW));
    int lb_hi = (int)floorf((lo + dphi) * (1.0f / LONW));
    int nb = lb_hi - lb_lo + 1;
    if (nb > LB) { nb = LB; lb_lo = 0; }

    for (int t = 0; t < nb; ++t) {
        const int lb = (lb_lo + t) & (LB - 1);
        const int s  = g_binStart[lb * ZB + zlo];
        const int e  = g_binStart[lb * ZB + zhi + 1];    // contiguous z-run
        for (int j = s + lane; j < e; j += 32) {
            float4 p = g_sorted[j];
            float d2 = __fsub_rn(__fadd_rn(g2, p.w),
                       __fmul_rn(2.0f, __fmaf_rn(z, p.z,
                                       __fmaf_rn(y, p.y,
                                       __fmul_rn(x, p.x)))));
            int vi = g_sidx[j];
            if (d2 < dd[7] || (d2 == dd[7] && vi < xi[7])) {   // rare
                float v = d2;
#pragma unroll
                for (int tt = 0; tt < 8; ++tt) {
                    bool sw = lex_less(v, vi, dd[tt], xi[tt]);
                    float nv = sw ? dd[tt] : v;
                    int   ni = sw ? xi[tt] : vi;
                    dd[tt] = sw ? v  : dd[tt];
                    xi[tt] = sw ? vi : xi[tt];
                    v = nv; vi = ni;
                }
            }
        }
    }

    // warp-merge: 8 rounds of lex argmin over lane heads (stable top-8)
    float myd = 0.f; int myi = 0;
#pragma unroll
    for (int r = 0; r < 8; ++r) {
        float bv = dd[0]; int bi = xi[0]; int bl = lane;
#pragma unroll
        for (int off = 16; off > 0; off >>= 1) {
            float ov = __shfl_down_sync(0xffffffffu, bv, off);
            int   oi = __shfl_down_sync(0xffffffffu, bi, off);
            int   ol = __shfl_down_sync(0xffffffffu, bl, off);
            if (lex_less(ov, oi, bv, bi)) { bv = ov; bi = oi; bl = ol; }
        }
        bv = __shfl_sync(0xffffffffu, bv, 0);
        bi = __shfl_sync(0xffffffffu, bi, 0);
        bl = __shfl_sync(0xffffffffu, bl, 0);
        if (lane == bl) {
#pragma unroll
            for (int j = 0; j < 7; ++j) { dd[j] = dd[j+1]; xi[j] = xi[j+1]; }
            dd[7] = FLT_MAX; xi[7] = 0x7fffffff;
        }
        if (lane == r) { myd = bv; myi = bi; }
    }

    // softmax over -dist among the 8 (lanes 0..7); rank0 = nearest
    float dist = sqrtf(fmaxf(myd, 1e-12f));
    float dmn  = __shfl_sync(0xffffffffu, dist, 0);
    float ww = 0.f;
    if (lane < 8) ww = expf(__fsub_rn(dmn, dist));
    float ssum = ww;
#pragma unroll
    for (int off = 16; off > 0; off >>= 1) ssum += __shfl_xor_sync(0xffffffffu, ssum, off);
    if (lane < 8) {
        g_knw[w * 8 + lane] = __fdiv_rn(ww, ssum);
        g_kni[w * 8 + lane] = myi;
    }
}

// ---------------------------------------------------------------------------
// Gather: out[b][c'][g] = bias[c'] + sum_k w_k * MW[b][idx_k][c'].
// Block = 8 consecutive g, 256 threads = (b, c'). Gathered MW rows are
// L2-resident; each load is one 128B warp-coalesced line.
// ---------------------------------------------------------------------------
__global__ __launch_bounds__(256) void gather_kernel(const float* __restrict__ bias,
                                                     float* __restrict__ out) {
    __shared__ float s_w[8][8];
    __shared__ int   s_i[8][8];

    const int tid = threadIdx.x;
    const int g0  = blockIdx.x * 8;

    if (tid < 64) {
        int gg = tid >> 3, k = tid & 7;
        int g = g0 + gg;
        if (g < NG) { s_w[gg][k] = g_knw[g * 8 + k]; s_i[gg][k] = g_kni[g * 8 + k]; }
        else        { s_w[gg][k] = 0.f;              s_i[gg][k] = 0; }
    }
    __syncthreads();

    const int b = tid >> 6;
    const int c = tid & 63;
    const float bv = bias[c];
    const float* Mb = g_MW + (size_t)b * NODES * CH + c;

    float r[8];
#pragma unroll
    for (int gg = 0; gg < 8; ++gg) {
        float a = bv;
#pragma unroll
        for (int k = 0; k < 8; ++k)
            a = __fmaf_rn(s_w[gg][k], Mb[(size_t)s_i[gg][k] * CH], a);
        r[gg] = a;
    }

    float* op = out + (size_t)(b * CH + c) * NG + g0;
    if (g0 + 8 <= NG) {
        ((float4*)op)[0] = make_float4(r[0], r[1], r[2], r[3]);
        ((float4*)op)[1] = make_float4(r[4], r[5], r[6], r[7]);
    } else {
#pragma unroll
        for (int gg = 0; gg < 8; ++gg)
            if (g0 + gg < NG) op[gg] = r[gg];
    }
}

// ---------------------------------------------------------------------------
extern "C" void kernel_launch(void* const* d_in, const int* in_sizes, int n_in,
                              void* d_out, int out_size) {
    const float* mesh_output   = (const float*)d_in[0];  // (4,10242,64)
    const float* mesh_vertices = (const float*)d_in[1];  // (10242,3)
    const float* lat           = (const float*)d_in[2];  // (91,)
    const float* lon           = (const float*)d_in[3];  // (180,)
    const float* W             = (const float*)d_in[4];  // (64,64)
    const float* bvec          = (const float*)d_in[5];  // (64,)
    float* out = (float*)d_out;                          // (4,64,91,180)

    zero_tw_kernel<<<NBIN2 / 256, 256>>>(W);
    hist_kernel<<<(NODES + 255) / 256, 256>>>(mesh_vertices);
    scan_kernel<<<1, 256>>>();
    scatter_kernel<<<(NODES + 255) / 256, 256>>>(mesh_vertices);
    gemm_kernel<<<(NROWS + 31) / 32, 256>>>(mesh_output);
    knn_kernel<<<(NG + 7) / 8, 256>>>(lat, lon);
    gather_kernel<<<(NG + 7) / 8, 256>>>(bvec, out);
}